// round 9
// baseline (speedup 1.0000x reference)
#include <cuda_runtime.h>

#define B_    2
#define QLEN  2048
#define HID   2048
#define NH    16
#define NKV   4
#define HD    128
#define BK    16

// Scratch (device globals are the sanctioned scratch mechanism)
__device__ float g_q [(size_t)B_ * NH * QLEN * HD];   // (b,h,q,d) 32MB
__device__ float g_ao[(size_t)B_ * QLEN * NH * HD];   // (b,q,h,d) 32MB

typedef unsigned long long ull;

// tf32 round-to-nearest (unbiased; applied once at SMEM/fragment build time)
__device__ __forceinline__ float tf32r(float x) {
    unsigned u; asm("cvt.rna.tf32.f32 %0, %1;" : "=r"(u) : "f"(x));
    return __uint_as_float(u);
}
__device__ __forceinline__ unsigned tf32u(float x) {
    unsigned u; asm("cvt.rna.tf32.f32 %0, %1;" : "=r"(u) : "f"(x));
    return u;
}
__device__ __forceinline__ float4 tf32r4(float4 v) {
    return make_float4(tf32r(v.x), tf32r(v.y), tf32r(v.z), tf32r(v.w));
}

__device__ __forceinline__ void mma_tf32(float* c, const unsigned* a, const unsigned* b) {
    asm("mma.sync.aligned.m16n8k8.row.col.f32.tf32.tf32.f32 "
        "{%0,%1,%2,%3}, {%4,%5,%6,%7}, {%8,%9}, {%0,%1,%2,%3};"
        : "+f"(c[0]), "+f"(c[1]), "+f"(c[2]), "+f"(c[3])
        : "r"(a[0]), "r"(a[1]), "r"(a[2]), "r"(a[3]), "r"(b[0]), "r"(b[1]));
}

// ---------------------------------------------------------------------------
// 128x128 tf32 tensor-core GEMM. 4 warps (2x2), warp tile 64x64 = 4x8 atoms
// of m16n8k8 -> fragment reuse 4x8: 1.0 LDS/MMA (was 1.5 at 64x32 tiles),
// cutting smem crossbar bytes 33% (the R8-measured 70.5% L1 bound).
// BK=16, double-buffered SMEM (stride 136 = conflict-free), one sync/k-step.
// QMODE=1: scatter into g_q as (b,h,q,d) + bias. QMODE=0: row-major C.
// ---------------------------------------------------------------------------
#define GSTR 136

template <int QMODE>
__global__ void __launch_bounds__(128, 2)
tgemm128(const float* __restrict__ A, const float* __restrict__ Bm,
         const float* __restrict__ bias, float* __restrict__ C,
         int M, int N, int K)
{
    __shared__ float As[2][BK][GSTR];   // [k][m], tf32-rounded
    __shared__ float Bs[2][BK][GSTR];   // [k][n], tf32-rounded

    int tid = threadIdx.x;
    int w = tid >> 5, l = tid & 31;
    int wr = w >> 1, wc = w & 1;          // warp grid 2x2, tiles 64x64
    int gid = l >> 2, tg = l & 3;
    int bx = blockIdx.x, by = blockIdx.y;

    float c[4][8][4];
#pragma unroll
    for (int i = 0; i < 4; i++)
#pragma unroll
        for (int j = 0; j < 8; j++)
#pragma unroll
            for (int r = 0; r < 4; r++) c[i][j][r] = 0.f;

    int am = tid;                          // A loader: 1 row, 16 k per thread
    int bk = tid >> 3, bn = (tid & 7) * 16;  // B loader: 16 k x 128 n
    const float* Ap = A + (size_t)(by * 128 + am) * K;
    const float* Bp = Bm + (size_t)bk * N + bx * 128 + bn;

    float4 av[4], bv[4];
#pragma unroll
    for (int i = 0; i < 4; i++) {
        av[i] = *(const float4*)(Ap + i * 4);
        bv[i] = *(const float4*)(Bp + i * 4);
    }

    // prologue store, buffer 0
#pragma unroll
    for (int i = 0; i < 4; i++) {
        As[0][i*4+0][am] = tf32r(av[i].x); As[0][i*4+1][am] = tf32r(av[i].y);
        As[0][i*4+2][am] = tf32r(av[i].z); As[0][i*4+3][am] = tf32r(av[i].w);
        *(float4*)&Bs[0][bk][bn + i*4] = tf32r4(bv[i]);
    }
    __syncthreads();

    int p = 0;
    for (int kt = 0; kt < K; kt += BK) {
        bool more = (kt + BK) < K;
        if (more) {
#pragma unroll
            for (int i = 0; i < 4; i++) {
                av[i] = *(const float4*)(Ap + kt + BK + i * 4);
                bv[i] = *(const float4*)(Bp + (size_t)(kt + BK) * N + i * 4);
            }
        }
#pragma unroll
        for (int ka = 0; ka < 2; ka++) {
            int kb = ka * 8;
            unsigned bf[8][2];
#pragma unroll
            for (int nj = 0; nj < 8; nj++) {
                int nb = wc * 64 + nj * 8 + gid;
                bf[nj][0] = __float_as_uint(Bs[p][kb + tg    ][nb]);
                bf[nj][1] = __float_as_uint(Bs[p][kb + tg + 4][nb]);
            }
#pragma unroll
            for (int mi = 0; mi < 4; mi++) {
                int mb = wr * 64 + mi * 16;
                unsigned af[4];
                af[0] = __float_as_uint(As[p][kb + tg    ][mb + gid]);
                af[1] = __float_as_uint(As[p][kb + tg    ][mb + gid + 8]);
                af[2] = __float_as_uint(As[p][kb + tg + 4][mb + gid]);
                af[3] = __float_as_uint(As[p][kb + tg + 4][mb + gid + 8]);
#pragma unroll
                for (int nj = 0; nj < 8; nj++)
                    mma_tf32(c[mi][nj], af, bf[nj]);
            }
        }
        if (more) {
            int q = p ^ 1;
#pragma unroll
            for (int i = 0; i < 4; i++) {
                As[q][i*4+0][am] = tf32r(av[i].x); As[q][i*4+1][am] = tf32r(av[i].y);
                As[q][i*4+2][am] = tf32r(av[i].z); As[q][i*4+3][am] = tf32r(av[i].w);
                *(float4*)&Bs[q][bk][bn + i*4] = tf32r4(bv[i]);
            }
            __syncthreads();
            p = q;
        }
    }

    // epilogue
#pragma unroll
    for (int mi = 0; mi < 4; mi++) {
#pragma unroll
        for (int nj = 0; nj < 8; nj++) {
            int row0 = by * 128 + wr * 64 + mi * 16 + gid;
            int col0 = bx * 128 + wc * 64 + nj * 8 + tg * 2;
            float b0 = bias ? bias[col0] : 0.f;
            float b1 = bias ? bias[col0 + 1] : 0.f;
            float2 v0 = make_float2(c[mi][nj][0] + b0, c[mi][nj][1] + b1);
            float2 v1 = make_float2(c[mi][nj][2] + b0, c[mi][nj][3] + b1);
            if (QMODE) {
                int b  = row0 >> 11, q = row0 & (QLEN - 1);
                int h  = col0 >> 7,  d = col0 & (HD - 1);
                *(float2*)&g_q[(((size_t)(b * NH + h)) * QLEN + q) * HD + d] = v0;
                int rb = (row0 + 8) >> 11, rq = (row0 + 8) & (QLEN - 1);
                *(float2*)&g_q[(((size_t)(rb * NH + h)) * QLEN + rq) * HD + d] = v1;
            } else {
                *(float2*)&C[(size_t)row0 * N + col0]       = v0;
                *(float2*)&C[(size_t)(row0 + 8) * N + col0] = v1;
            }
        }
    }
}

// ---------------------------------------------------------------------------
// RoPE in-place on g_q. One thread per (b,h,q,d<64) pair.
// ---------------------------------------------------------------------------
__global__ void rope_kernel(const float* __restrict__ cosp, const float* __restrict__ sinp)
{
    int t = blockIdx.x * blockDim.x + threadIdx.x;
    int d = t & 63;
    int q = (t >> 6) & (QLEN - 1);
    int bh = t >> 17;
    int b = bh >> 4;
    size_t base  = ((size_t)bh * QLEN + q) * HD;
    size_t cbase = ((size_t)b * QLEN + q) * HD;
    float x1 = g_q[base + d], x2 = g_q[base + d + 64];
    float c1 = cosp[cbase + d],      s1 = sinp[cbase + d];
    float c2 = cosp[cbase + d + 64], s2 = sinp[cbase + d + 64];
    g_q[base + d]      = x1 * c1 - x2 * s1;
    g_q[base + d + 64] = x2 * c2 + x1 * s2;
}

// ---------------------------------------------------------------------------
// Tensor-core glide attention. CTA = 128 threads (4 warps), 64-query tile.
// Warp w owns q rows [16w,16w+16) x full 64-key tiles -> softmax is warp-local.
// ALL MMA operands (Q, K, P, V) are tf32 ROUND-TO-NEAREST (unbiased).
// SMEM pads: Ks stride 132, Vs 136, Ps 68 — fragment LDS conflict-free.
// Heavy CTAs launched first (LPT).
// ---------------------------------------------------------------------------
#define ATT2_SMEM_BYTES ((64*132 + 64*136 + 64*68) * 4)

__global__ void __launch_bounds__(128, 2)
attn_tc(const float* __restrict__ Kc, const float* __restrict__ Vc)
{
    extern __shared__ float sm[];
    float* Ks = sm;                 // [64][132]  keys row-major, tf32-RN
    float* Vs = Ks + 64 * 132;      // [64][136]  values row-major, tf32-RN
    float* Ps = Vs + 64 * 136;      // [64][68]   probs, tf32-RN
    float* Qs = sm;                 // staging, aliases Ks (used before loop)

    const float SCALE = 0.08838834764831843f;  // 128^-0.5

    int tid = threadIdx.x;
    int w = tid >> 5, l = tid & 31;
    int gid = l >> 2, tg = l & 3;
    int qi = (gridDim.x - 1) - blockIdx.x;   // heavy tiles first
    int h = blockIdx.y, b = blockIdx.z;
    int q0 = qi * 64;
    int kvh = h >> 2;
    int qrow = w * 16;                        // warp's q base within tile

    // stage Q, build tf32-RN A fragments in registers, then release staging
    {
        const float* qg = &g_q[(((size_t)(b * NH + h)) * QLEN + q0) * HD];
        for (int i = tid; i < 64 * 32; i += 128) {
            int r = i >> 5, c4 = (i & 31) << 2;
            *(float4*)&Qs[r * 132 + c4] = *(const float4*)&qg[r * HD + c4];
        }
    }
    __syncthreads();
    unsigned qa[16][4];
#pragma unroll
    for (int ks = 0; ks < 16; ks++) {
        int col = ks * 8 + tg;
        qa[ks][0] = tf32u(Qs[(qrow + gid    ) * 132 + col]);
        qa[ks][1] = tf32u(Qs[(qrow + gid + 8) * 132 + col]);
        qa[ks][2] = tf32u(Qs[(qrow + gid    ) * 132 + col + 4]);
        qa[ks][3] = tf32u(Qs[(qrow + gid + 8) * 132 + col + 4]);
    }

    float oc[16][4];
#pragma unroll
    for (int j = 0; j < 16; j++)
#pragma unroll
        for (int r = 0; r < 4; r++) oc[j][r] = 0.f;
    float m_run[2] = {-1e30f, -1e30f};
    float l_run[2] = {0.f, 0.f};

    int ntiles = qi + 1;

    for (int t = 0; t < ntiles; t++) {
        int k0 = t * 64;
        bool masked = (t == ntiles - 1);
        __syncthreads();   // previous tile's Ks/Vs readers done (also covers Qs)

        // load K,V tiles, tf32-RN at store (row = key, d contiguous)
        for (int i = tid; i < 64 * 32; i += 128) {
            int r = i >> 5, c4 = (i & 31) << 2;
            size_t src = (((size_t)(b * QLEN) + k0 + r) * NKV + kvh) * HD + c4;
            *(float4*)&Ks[r * 132 + c4] = tf32r4(*(const float4*)&Kc[src]);
            *(float4*)&Vs[r * 136 + c4] = tf32r4(*(const float4*)&Vc[src]);
        }
        __syncthreads();

        // ---- S = Q K^T : 16 k-steps(d) x 8 n-atoms(keys) ----
        float sc[8][4];
#pragma unroll
        for (int j = 0; j < 8; j++)
#pragma unroll
            for (int r = 0; r < 4; r++) sc[j][r] = 0.f;
#pragma unroll
        for (int ks = 0; ks < 16; ks++) {
            int d0 = ks * 8 + tg;
#pragma unroll
            for (int j = 0; j < 8; j++) {
                unsigned bf[2];
                bf[0] = __float_as_uint(Ks[(j * 8 + gid) * 132 + d0]);
                bf[1] = __float_as_uint(Ks[(j * 8 + gid) * 132 + d0 + 4]);
                mma_tf32(sc[j], qa[ks], bf);
            }
        }

        // ---- warp-local online softmax (rows gid, gid+8) ----
        float alpha_h[2];
#pragma unroll
        for (int hf = 0; hf < 2; hf++) {
            int rowq = q0 + qrow + gid + hf * 8;
            int kend = masked ? ((rowq < 4) ? 4 : (rowq & ~3)) : (1 << 30);
            float mx = -1e30f;
#pragma unroll
            for (int j = 0; j < 8; j++) {
#pragma unroll
                for (int cc = 0; cc < 2; cc++) {
                    float v = sc[j][hf * 2 + cc] * SCALE;
                    int col = k0 + j * 8 + tg * 2 + cc;
                    if (col >= kend) v = -1e30f;
                    sc[j][hf * 2 + cc] = v;
                    mx = fmaxf(mx, v);
                }
            }
            mx = fmaxf(mx, __shfl_xor_sync(0xffffffffu, mx, 1));
            mx = fmaxf(mx, __shfl_xor_sync(0xffffffffu, mx, 2));
            float mn = fmaxf(m_run[hf], mx);
            float al = __expf(m_run[hf] - mn);
            m_run[hf] = mn;
            float sum = 0.f;
#pragma unroll
            for (int j = 0; j < 8; j++) {
                // round P to tf32 BEFORE summing so l_run matches the PV numerator
                float p0 = tf32r(__expf(sc[j][hf * 2]     - mn));
                float p1 = tf32r(__expf(sc[j][hf * 2 + 1] - mn));
                sum += p0 + p1;
                *(float2*)&Ps[(qrow + gid + hf * 8) * 68 + j * 8 + tg * 2] =
                    make_float2(p0, p1);
            }
            sum += __shfl_xor_sync(0xffffffffu, sum, 1);
            sum += __shfl_xor_sync(0xffffffffu, sum, 2);
            l_run[hf] = l_run[hf] * al + sum;
            alpha_h[hf] = al;
        }
        __syncwarp();   // Ps rows are warp-exclusive; order STS -> LDS in-warp

        // rescale running O
#pragma unroll
        for (int j = 0; j < 16; j++) {
            oc[j][0] *= alpha_h[0]; oc[j][1] *= alpha_h[0];
            oc[j][2] *= alpha_h[1]; oc[j][3] *= alpha_h[1];
        }

        // ---- O += P V : 8 k-steps(keys) x 16 n-atoms(d) ----
#pragma unroll
        for (int kbi = 0; kbi < 8; kbi++) {
            int kb = kbi * 8;
            unsigned af[4];
            af[0] = __float_as_uint(Ps[(qrow + gid    ) * 68 + kb + tg]);
            af[1] = __float_as_uint(Ps[(qrow + gid + 8) * 68 + kb + tg]);
            af[2] = __float_as_uint(Ps[(qrow + gid    ) * 68 + kb + tg + 4]);
            af[3] = __float_as_uint(Ps[(qrow + gid + 8) * 68 + kb + tg + 4]);
#pragma unroll
            for (int j = 0; j < 16; j++) {
                unsigned bf[2];
                bf[0] = __float_as_uint(Vs[(kb + tg    ) * 136 + j * 8 + gid]);
                bf[1] = __float_as_uint(Vs[(kb + tg + 4) * 136 + j * 8 + gid]);
                mma_tf32(oc[j], af, bf);
            }
        }
    }

    // normalize + store to (b,q,h,d)
    float inv0 = 1.0f / l_run[0];
    float inv1 = 1.0f / l_run[1];
    int row0 = q0 + qrow + gid;
#pragma unroll
    for (int j = 0; j < 16; j++) {
        int d = j * 8 + tg * 2;
        *(float2*)&g_ao[(((size_t)b * QLEN + row0) * NH + h) * HD + d] =
            make_float2(oc[j][0] * inv0, oc[j][1] * inv0);
        *(float2*)&g_ao[(((size_t)b * QLEN + row0 + 8) * NH + h) * HD + d] =
            make_float2(oc[j][2] * inv1, oc[j][3] * inv1);
    }
}

// ---------------------------------------------------------------------------
extern "C" void kernel_launch(void* const* d_in, const int* in_sizes, int n_in,
                              void* d_out, int out_size)
{
    const float* X    = (const float*)d_in[0];
    const float* Kc   = (const float*)d_in[1];
    const float* Vc   = (const float*)d_in[2];
    const float* cosp = (const float*)d_in[3];
    const float* sinp = (const float*)d_in[4];
    const float* Wq   = (const float*)d_in[5];
    const float* bq   = (const float*)d_in[6];
    const float* Wo   = (const float*)d_in[7];
    float* out = (float*)d_out;

    void* gaop;
    cudaGetSymbolAddress(&gaop, g_ao);

    // 1) Q projection (tf32 tensor cores) + bias, scattered to (b,h,q,d)
    tgemm128<1><<<dim3(HID / 128, (B_ * QLEN) / 128), 128>>>(
        X, Wq, bq, nullptr, B_ * QLEN, NH * HD, HID);

    // 2) RoPE in place
    rope_kernel<<<(B_ * NH * QLEN * 64) / 256, 256>>>(cosp, sinp);

    // 3) glide attention (tensor cores, tf32-RN operands)
    cudaFuncSetAttribute(attn_tc, cudaFuncAttributeMaxDynamicSharedMemorySize,
                         ATT2_SMEM_BYTES);
    attn_tc<<<dim3(QLEN / 64, NH, B_), 128, ATT2_SMEM_BYTES>>>(Kc, Vc);

    // 4) output projection (tf32 tensor cores)
    tgemm128<0><<<dim3(HID / 128, (B_ * QLEN) / 128), 128>>>(
        (const float*)gaop, Wo, nullptr, out, B_ * QLEN, HID, NH * HD);
}

// round 10
// speedup vs baseline: 1.1835x; 1.1835x over previous
#include <cuda_runtime.h>

#define B_    2
#define QLEN  2048
#define HID   2048
#define NH    16
#define NKV   4
#define HD    128
#define BK    16

// Scratch (device globals are the sanctioned scratch mechanism)
__device__ float g_q [(size_t)B_ * NH * QLEN * HD];   // (b,h,q,d) 32MB, pre-RoPE
__device__ float g_ao[(size_t)B_ * QLEN * NH * HD];   // (b,q,h,d) 32MB

typedef unsigned long long ull;

// tf32 round-to-nearest (unbiased; applied once at SMEM/fragment build time)
__device__ __forceinline__ float tf32r(float x) {
    unsigned u; asm("cvt.rna.tf32.f32 %0, %1;" : "=r"(u) : "f"(x));
    return __uint_as_float(u);
}
__device__ __forceinline__ unsigned tf32u(float x) {
    unsigned u; asm("cvt.rna.tf32.f32 %0, %1;" : "=r"(u) : "f"(x));
    return u;
}
__device__ __forceinline__ float4 tf32r4(float4 v) {
    return make_float4(tf32r(v.x), tf32r(v.y), tf32r(v.z), tf32r(v.w));
}

__device__ __forceinline__ void mma_tf32(float* c, const unsigned* a, const unsigned* b) {
    asm("mma.sync.aligned.m16n8k8.row.col.f32.tf32.tf32.f32 "
        "{%0,%1,%2,%3}, {%4,%5,%6,%7}, {%8,%9}, {%0,%1,%2,%3};"
        : "+f"(c[0]), "+f"(c[1]), "+f"(c[2]), "+f"(c[3])
        : "r"(a[0]), "r"(a[1]), "r"(a[2]), "r"(a[3]), "r"(b[0]), "r"(b[1]));
}

// ---------------------------------------------------------------------------
// 128x128 tf32 tensor-core GEMM — R8 configuration (the measured optimum:
// 8 warps 2x4, warp tile 64x32, 16 warps/SM; 64x64 tiles regressed via
// register pressure -> occupancy collapse in R9).
// BK=16, double-buffered SMEM (stride 136 = conflict-free), one sync/k-step.
// QMODE=1: scatter into g_q as (b,h,q,d) + bias. QMODE=0: row-major C.
// ---------------------------------------------------------------------------
#define GSTR 136

template <int QMODE>
__global__ void __launch_bounds__(256, 2)
tgemm128(const float* __restrict__ A, const float* __restrict__ Bm,
         const float* __restrict__ bias, float* __restrict__ C,
         int M, int N, int K)
{
    __shared__ float As[2][BK][GSTR];   // [k][m], tf32-rounded
    __shared__ float Bs[2][BK][GSTR];   // [k][n], tf32-rounded

    int tid = threadIdx.x;
    int w = tid >> 5, l = tid & 31;
    int wr = w >> 2, wc = w & 3;          // warp grid 2x4
    int gid = l >> 2, tg = l & 3;
    int bx = blockIdx.x, by = blockIdx.y;

    float c[4][4][4];
#pragma unroll
    for (int i = 0; i < 4; i++)
#pragma unroll
        for (int j = 0; j < 4; j++)
#pragma unroll
            for (int r = 0; r < 4; r++) c[i][j][r] = 0.f;

    int am = tid >> 1, ak = (tid & 1) * 8;   // A loader: 128 rows x 16 k
    int bk = tid >> 4, bn = (tid & 15) * 8;  // B loader: 16 k x 128 n
    const float* Ap = A + (size_t)(by * 128 + am) * K + ak;
    const float* Bp = Bm + (size_t)bk * N + bx * 128 + bn;

    float4 av0 = *(const float4*)(Ap);
    float4 av1 = *(const float4*)(Ap + 4);
    float4 bv0 = *(const float4*)(Bp);
    float4 bv1 = *(const float4*)(Bp + 4);

    // prologue store, buffer 0
    {
        As[0][ak+0][am] = tf32r(av0.x); As[0][ak+1][am] = tf32r(av0.y);
        As[0][ak+2][am] = tf32r(av0.z); As[0][ak+3][am] = tf32r(av0.w);
        As[0][ak+4][am] = tf32r(av1.x); As[0][ak+5][am] = tf32r(av1.y);
        As[0][ak+6][am] = tf32r(av1.z); As[0][ak+7][am] = tf32r(av1.w);
        *(float4*)&Bs[0][bk][bn]     = tf32r4(bv0);
        *(float4*)&Bs[0][bk][bn + 4] = tf32r4(bv1);
    }
    __syncthreads();

    int p = 0;
    for (int kt = 0; kt < K; kt += BK) {
        bool more = (kt + BK) < K;
        if (more) {
            av0 = *(const float4*)(Ap + kt + BK);
            av1 = *(const float4*)(Ap + kt + BK + 4);
            bv0 = *(const float4*)(Bp + (size_t)(kt + BK) * N);
            bv1 = *(const float4*)(Bp + (size_t)(kt + BK) * N + 4);
        }
#pragma unroll
        for (int ka = 0; ka < 2; ka++) {
            int kb = ka * 8;
            unsigned bf[4][2];
#pragma unroll
            for (int nj = 0; nj < 4; nj++) {
                int nb = wc * 32 + nj * 8 + gid;
                bf[nj][0] = __float_as_uint(Bs[p][kb + tg    ][nb]);
                bf[nj][1] = __float_as_uint(Bs[p][kb + tg + 4][nb]);
            }
#pragma unroll
            for (int mi = 0; mi < 4; mi++) {
                int mb = wr * 64 + mi * 16;
                unsigned af[4];
                af[0] = __float_as_uint(As[p][kb + tg    ][mb + gid]);
                af[1] = __float_as_uint(As[p][kb + tg    ][mb + gid + 8]);
                af[2] = __float_as_uint(As[p][kb + tg + 4][mb + gid]);
                af[3] = __float_as_uint(As[p][kb + tg + 4][mb + gid + 8]);
#pragma unroll
                for (int nj = 0; nj < 4; nj++)
                    mma_tf32(c[mi][nj], af, bf[nj]);
            }
        }
        if (more) {
            int q = p ^ 1;
            As[q][ak+0][am] = tf32r(av0.x); As[q][ak+1][am] = tf32r(av0.y);
            As[q][ak+2][am] = tf32r(av0.z); As[q][ak+3][am] = tf32r(av0.w);
            As[q][ak+4][am] = tf32r(av1.x); As[q][ak+5][am] = tf32r(av1.y);
            As[q][ak+6][am] = tf32r(av1.z); As[q][ak+7][am] = tf32r(av1.w);
            *(float4*)&Bs[q][bk][bn]     = tf32r4(bv0);
            *(float4*)&Bs[q][bk][bn + 4] = tf32r4(bv1);
            __syncthreads();
            p = q;
        }
    }

    // epilogue
#pragma unroll
    for (int mi = 0; mi < 4; mi++) {
#pragma unroll
        for (int nj = 0; nj < 4; nj++) {
            int row0 = by * 128 + wr * 64 + mi * 16 + gid;
            int col0 = bx * 128 + wc * 32 + nj * 8 + tg * 2;
            float b0 = bias ? bias[col0] : 0.f;
            float b1 = bias ? bias[col0 + 1] : 0.f;
            float2 v0 = make_float2(c[mi][nj][0] + b0, c[mi][nj][1] + b1);
            float2 v1 = make_float2(c[mi][nj][2] + b0, c[mi][nj][3] + b1);
            if (QMODE) {
                int b  = row0 >> 11, q = row0 & (QLEN - 1);
                int h  = col0 >> 7,  d = col0 & (HD - 1);
                *(float2*)&g_q[(((size_t)(b * NH + h)) * QLEN + q) * HD + d] = v0;
                int rb = (row0 + 8) >> 11, rq = (row0 + 8) & (QLEN - 1);
                *(float2*)&g_q[(((size_t)(rb * NH + h)) * QLEN + rq) * HD + d] = v1;
            } else {
                *(float2*)&C[(size_t)row0 * N + col0]       = v0;
                *(float2*)&C[(size_t)(row0 + 8) * N + col0] = v1;
            }
        }
    }
}

// ---------------------------------------------------------------------------
// Tensor-core glide attention with FUSED RoPE on the Q tile at staging time
// (replaces the standalone rope kernel: saves its ~75MB of g_q traffic + a
// launch). CTA = 128 threads (4 warps), 64-query tile; warp w owns q rows
// [16w,16w+16) x full 64-key tiles -> softmax is warp-local.
// ALL MMA operands (Q, K, P, V) are tf32 ROUND-TO-NEAREST (unbiased).
// SMEM pads: Ks stride 132, Vs 136, Ps 68 — fragment LDS conflict-free.
// Heavy CTAs launched first (LPT).
// ---------------------------------------------------------------------------
#define ATT2_SMEM_BYTES ((64*132 + 64*136 + 64*68) * 4)

__global__ void __launch_bounds__(128, 2)
attn_tc(const float* __restrict__ Kc, const float* __restrict__ Vc,
        const float* __restrict__ cosp, const float* __restrict__ sinp)
{
    extern __shared__ float sm[];
    float* Ks = sm;                 // [64][132]  keys row-major, tf32-RN
    float* Vs = Ks + 64 * 132;      // [64][136]  values row-major, tf32-RN
    float* Ps = Vs + 64 * 136;      // [64][68]   probs, tf32-RN
    float* Qs = sm;                 // staging, aliases Ks (used before loop)

    const float SCALE = 0.08838834764831843f;  // 128^-0.5

    int tid = threadIdx.x;
    int w = tid >> 5, l = tid & 31;
    int gid = l >> 2, tg = l & 3;
    int qi = (gridDim.x - 1) - blockIdx.x;   // heavy tiles first
    int h = blockIdx.y, b = blockIdx.z;
    int q0 = qi * 64;
    int kvh = h >> 2;
    int qrow = w * 16;                        // warp's q base within tile

    // stage Q with fused RoPE: out[d]    = x[d]*cos[d]    - x[d+64]*sin[d]
    //                          out[d+64] = x[d+64]*cos[d+64] + x[d]*sin[d+64]
    {
        const float* qg = &g_q[(((size_t)(b * NH + h)) * QLEN + q0) * HD];
        for (int i = tid; i < 64 * 16; i += 128) {
            int r = i >> 4, p4 = (i & 15) << 2;        // row, pair-col (d<64)
            size_t cb = ((size_t)b * QLEN + q0 + r) * HD;
            float4 x1 = *(const float4*)&qg[r * HD + p4];
            float4 x2 = *(const float4*)&qg[r * HD + p4 + 64];
            float4 c1 = *(const float4*)&cosp[cb + p4];
            float4 s1 = *(const float4*)&sinp[cb + p4];
            float4 c2 = *(const float4*)&cosp[cb + p4 + 64];
            float4 s2 = *(const float4*)&sinp[cb + p4 + 64];
            *(float4*)&Qs[r * 132 + p4] = make_float4(
                x1.x * c1.x - x2.x * s1.x, x1.y * c1.y - x2.y * s1.y,
                x1.z * c1.z - x2.z * s1.z, x1.w * c1.w - x2.w * s1.w);
            *(float4*)&Qs[r * 132 + p4 + 64] = make_float4(
                x2.x * c2.x + x1.x * s2.x, x2.y * c2.y + x1.y * s2.y,
                x2.z * c2.z + x1.z * s2.z, x2.w * c2.w + x1.w * s2.w);
        }
    }
    __syncthreads();
    unsigned qa[16][4];
#pragma unroll
    for (int ks = 0; ks < 16; ks++) {
        int col = ks * 8 + tg;
        qa[ks][0] = tf32u(Qs[(qrow + gid    ) * 132 + col]);
        qa[ks][1] = tf32u(Qs[(qrow + gid + 8) * 132 + col]);
        qa[ks][2] = tf32u(Qs[(qrow + gid    ) * 132 + col + 4]);
        qa[ks][3] = tf32u(Qs[(qrow + gid + 8) * 132 + col + 4]);
    }

    float oc[16][4];
#pragma unroll
    for (int j = 0; j < 16; j++)
#pragma unroll
        for (int r = 0; r < 4; r++) oc[j][r] = 0.f;
    float m_run[2] = {-1e30f, -1e30f};
    float l_run[2] = {0.f, 0.f};

    int ntiles = qi + 1;

    for (int t = 0; t < ntiles; t++) {
        int k0 = t * 64;
        bool masked = (t == ntiles - 1);
        __syncthreads();   // previous tile's Ks/Vs readers done (also covers Qs)

        // load K,V tiles, tf32-RN at store (row = key, d contiguous)
        for (int i = tid; i < 64 * 32; i += 128) {
            int r = i >> 5, c4 = (i & 31) << 2;
            size_t src = (((size_t)(b * QLEN) + k0 + r) * NKV + kvh) * HD + c4;
            *(float4*)&Ks[r * 132 + c4] = tf32r4(*(const float4*)&Kc[src]);
            *(float4*)&Vs[r * 136 + c4] = tf32r4(*(const float4*)&Vc[src]);
        }
        __syncthreads();

        // ---- S = Q K^T : 16 k-steps(d) x 8 n-atoms(keys) ----
        float sc[8][4];
#pragma unroll
        for (int j = 0; j < 8; j++)
#pragma unroll
            for (int r = 0; r < 4; r++) sc[j][r] = 0.f;
#pragma unroll
        for (int ks = 0; ks < 16; ks++) {
            int d0 = ks * 8 + tg;
#pragma unroll
            for (int j = 0; j < 8; j++) {
                unsigned bf[2];
                bf[0] = __float_as_uint(Ks[(j * 8 + gid) * 132 + d0]);
                bf[1] = __float_as_uint(Ks[(j * 8 + gid) * 132 + d0 + 4]);
                mma_tf32(sc[j], qa[ks], bf);
            }
        }

        // ---- warp-local online softmax (rows gid, gid+8) ----
        float alpha_h[2];
#pragma unroll
        for (int hf = 0; hf < 2; hf++) {
            int rowq = q0 + qrow + gid + hf * 8;
            int kend = masked ? ((rowq < 4) ? 4 : (rowq & ~3)) : (1 << 30);
            float mx = -1e30f;
#pragma unroll
            for (int j = 0; j < 8; j++) {
#pragma unroll
                for (int cc = 0; cc < 2; cc++) {
                    float v = sc[j][hf * 2 + cc] * SCALE;
                    int col = k0 + j * 8 + tg * 2 + cc;
                    if (col >= kend) v = -1e30f;
                    sc[j][hf * 2 + cc] = v;
                    mx = fmaxf(mx, v);
                }
            }
            mx = fmaxf(mx, __shfl_xor_sync(0xffffffffu, mx, 1));
            mx = fmaxf(mx, __shfl_xor_sync(0xffffffffu, mx, 2));
            float mn = fmaxf(m_run[hf], mx);
            float al = __expf(m_run[hf] - mn);
            m_run[hf] = mn;
            float sum = 0.f;
#pragma unroll
            for (int j = 0; j < 8; j++) {
                // round P to tf32 BEFORE summing so l_run matches the PV numerator
                float p0 = tf32r(__expf(sc[j][hf * 2]     - mn));
                float p1 = tf32r(__expf(sc[j][hf * 2 + 1] - mn));
                sum += p0 + p1;
                *(float2*)&Ps[(qrow + gid + hf * 8) * 68 + j * 8 + tg * 2] =
                    make_float2(p0, p1);
            }
            sum += __shfl_xor_sync(0xffffffffu, sum, 1);
            sum += __shfl_xor_sync(0xffffffffu, sum, 2);
            l_run[hf] = l_run[hf] * al + sum;
            alpha_h[hf] = al;
        }
        __syncwarp();   // Ps rows are warp-exclusive; order STS -> LDS in-warp

        // rescale running O
#pragma unroll
        for (int j = 0; j < 16; j++) {
            oc[j][0] *= alpha_h[0]; oc[j][1] *= alpha_h[0];
            oc[j][2] *= alpha_h[1]; oc[j][3] *= alpha_h[1];
        }

        // ---- O += P V : 8 k-steps(keys) x 16 n-atoms(d) ----
#pragma unroll
        for (int kbi = 0; kbi < 8; kbi++) {
            int kb = kbi * 8;
            unsigned af[4];
            af[0] = __float_as_uint(Ps[(qrow + gid    ) * 68 + kb + tg]);
            af[1] = __float_as_uint(Ps[(qrow + gid + 8) * 68 + kb + tg]);
            af[2] = __float_as_uint(Ps[(qrow + gid    ) * 68 + kb + tg + 4]);
            af[3] = __float_as_uint(Ps[(qrow + gid + 8) * 68 + kb + tg + 4]);
#pragma unroll
            for (int j = 0; j < 16; j++) {
                unsigned bf[2];
                bf[0] = __float_as_uint(Vs[(kb + tg    ) * 136 + j * 8 + gid]);
                bf[1] = __float_as_uint(Vs[(kb + tg + 4) * 136 + j * 8 + gid]);
                mma_tf32(oc[j], af, bf);
            }
        }
    }

    // normalize + store to (b,q,h,d)
    float inv0 = 1.0f / l_run[0];
    float inv1 = 1.0f / l_run[1];
    int row0 = q0 + qrow + gid;
#pragma unroll
    for (int j = 0; j < 16; j++) {
        int d = j * 8 + tg * 2;
        *(float2*)&g_ao[(((size_t)b * QLEN + row0) * NH + h) * HD + d] =
            make_float2(oc[j][0] * inv0, oc[j][1] * inv0);
        *(float2*)&g_ao[(((size_t)b * QLEN + row0 + 8) * NH + h) * HD + d] =
            make_float2(oc[j][2] * inv1, oc[j][3] * inv1);
    }
}

// ---------------------------------------------------------------------------
extern "C" void kernel_launch(void* const* d_in, const int* in_sizes, int n_in,
                              void* d_out, int out_size)
{
    const float* X    = (const float*)d_in[0];
    const float* Kc   = (const float*)d_in[1];
    const float* Vc   = (const float*)d_in[2];
    const float* cosp = (const float*)d_in[3];
    const float* sinp = (const float*)d_in[4];
    const float* Wq   = (const float*)d_in[5];
    const float* bq   = (const float*)d_in[6];
    const float* Wo   = (const float*)d_in[7];
    float* out = (float*)d_out;

    void* gaop;
    cudaGetSymbolAddress(&gaop, g_ao);

    // 1) Q projection (tf32 tensor cores) + bias, scattered to (b,h,q,d)
    tgemm128<1><<<dim3(HID / 128, (B_ * QLEN) / 128), 256>>>(
        X, Wq, bq, nullptr, B_ * QLEN, NH * HD, HID);

    // 2) glide attention (tensor cores, tf32-RN operands, fused RoPE)
    cudaFuncSetAttribute(attn_tc, cudaFuncAttributeMaxDynamicSharedMemorySize,
                         ATT2_SMEM_BYTES);
    attn_tc<<<dim3(QLEN / 64, NH, B_), 128, ATT2_SMEM_BYTES>>>(Kc, Vc, cosp, sinp);

    // 3) output projection (tf32 tensor cores)
    tgemm128<0><<<dim3(HID / 128, (B_ * QLEN) / 128), 256>>>(
        (const float*)gaop, Wo, nullptr, out, B_ * QLEN, HID, NH * HD);
}